// round 1
// baseline (speedup 1.0000x reference)
#include <cuda_runtime.h>
#include <cuda_bf16.h>
#include <cstdint>

// ============================================================================
// DotProductAttention: B=8, Q=2048, K=2048, D=512, fp32.
// Reference semantics: masked (k >= valid_len) LOGITS are replaced by 0.0
// (not -inf) before softmax over ALL keys. So masked keys contribute weight
// exp(0 - M) each and value Vtail = sum_{k>=L} V[k].
// Strategy: flash attention over VALID keys only (saves ~50% FLOPs on avg),
// then analytic tail correction:
//   M = max(m_valid, 0); c = exp(m_valid - M); w0 = exp(-M)
//   out = (o*c + w0*Vtail) / (l*c + (K-L)*w0)
// (Branch-free: when L==K, K-L==0 and Vtail==0, and the scaling cancels.)
// Math: fp32 with packed fma.rn.f32x2 (FFMA2) for 2x fp32 FMA throughput.
// ============================================================================

#define BB   8
#define QQ   2048
#define KK   2048
#define DD   512

typedef unsigned long long ull;

__device__ __forceinline__ ull pack2(float x, float y) {
    ull r;
    asm("mov.b64 %0, {%1, %2};" : "=l"(r) : "f"(x), "f"(y));
    return r;
}
__device__ __forceinline__ void unpack2(ull v, float& x, float& y) {
    asm("mov.b64 {%0, %1}, %2;" : "=f"(x), "=f"(y) : "l"(v));
}
__device__ __forceinline__ ull fma2(ull a, ull b, ull c) {
    ull d;
    asm("fma.rn.f32x2 %0, %1, %2, %3;" : "=l"(d) : "l"(a), "l"(b), "l"(c));
    return d;
}
__device__ __forceinline__ ull mul2_(ull a, ull b) {
    ull d;
    asm("mul.rn.f32x2 %0, %1, %2;" : "=l"(d) : "l"(a), "l"(b));
    return d;
}

// Scratch for deterministic Vtail computation (no atomics => deterministic).
__device__ __align__(16) float g_partial[BB][16][DD];
__device__ __align__(16) float g_vtail[BB][DD];

// ---------------------------------------------------------------------------
// Kernel 1: partial tail sums. CTA (s, b) sums V rows in [s*128,(s+1)*128) ∩ [L,K)
// ---------------------------------------------------------------------------
__global__ void vtail_partial_kernel(const float* __restrict__ V,
                                     const int* __restrict__ lens) {
    int s = blockIdx.x, b = blockIdx.y, d = threadIdx.x;
    int L = lens[b]; L = L < 1 ? 1 : (L > KK ? KK : L);
    int k0 = s * 128, k1 = k0 + 128;
    int ks = k0 < L ? L : k0;
    float a = 0.f;
    const float* vp = V + ((size_t)b * KK) * DD + d;
    for (int k = ks; k < k1; k++) a += vp[(size_t)k * DD];
    g_partial[b][s][d] = a;
}

// Kernel 2: reduce 16 partials -> Vtail (deterministic order)
__global__ void vtail_reduce_kernel() {
    int b = blockIdx.x, d = threadIdx.x;
    float a = 0.f;
#pragma unroll
    for (int s = 0; s < 16; s++) a += g_partial[b][s][d];
    g_vtail[b][d] = a;
}

// ---------------------------------------------------------------------------
// Main fused flash-attention kernel.
// Grid: (Q/64, B). Block: 512 threads.
// Tile: MQ=64 queries x NK=64 keys. O accumulator in registers (64 f32/thread).
// ---------------------------------------------------------------------------
__global__ void __launch_bounds__(512, 1)
attn_kernel(const float* __restrict__ Qp, const float* __restrict__ Kp,
            const float* __restrict__ Vp, const int* __restrict__ lens,
            float* __restrict__ out) {
    const int b = blockIdx.y;
    const int qbase = blockIdx.x * 64;
    const int t = threadIdx.x;

    // --- shared memory -----------------------------------------------------
    // sP: post-gemm1 scores / probabilities [64][68] (padded rows)
    __shared__ __align__(16) float sP[64][68];
    __shared__ float s_m[64], s_l[64], s_c[64];
    // union region: gemm1 staging (QT2 dup + KT transposed) OR V chunk
    __shared__ __align__(16) unsigned char sU[16384];
    ull   (*sQT2)[66] = (ull(*)[66])sU;                    // 16*66*8 = 8448 B
    float (*sKT)[68]  = (float(*)[68])(sU + 8448);         // 16*68*4 = 4352 B
    float* sV = (float*)sU;                                // 8*512*4 = 16384 B

    int L = lens[b]; L = L < 1 ? 1 : (L > KK ? KK : L);
    const int nt = (L + 63) >> 6;

    // thread roles
    const int ty  = t >> 4;    // 0..31 : gemm1 owns rows {2ty, 2ty+1}
    const int tx  = t & 15;    // 0..15 : gemm1 owns cols {4tx..4tx+3}
    const int m_o = t >> 3;    // 0..63 : gemm2/softmax row
    const int sg  = t & 7;     // 0..7  : gemm2 d-segment (64 floats each)

    // loader role: threads [0,256) load Q chunk, [256,512) load K chunk
    const bool isQ = t < 256;
    const int lrow = (t & 255) >> 2;        // 0..63
    const int ld4  = (t & 3) << 2;          // 0,4,8,12
    const float* gQrow = Qp + ((size_t)(b * QQ + qbase + lrow)) * DD + ld4;

    if (t < 64) { s_m[t] = -INFINITY; s_l[t] = 0.f; }

    ull o2[32];
#pragma unroll
    for (int i = 0; i < 32; i++) o2[i] = 0ull;
    __syncthreads();

    for (int kt = 0; kt < nt; kt++) {
        const float* gKtile =
            Kp + ((size_t)(b * KK + kt * 64 + lrow)) * DD + ld4;

        // ================= GEMM1: S[64][64] = Q[64][512] * K[64][512]^T ====
        ull a00 = 0, a01 = 0, a10 = 0, a11 = 0;
        float4 pf = isQ ? *(const float4*)gQrow : *(const float4*)gKtile;
#pragma unroll 1
        for (int c = 0; c < 32; c++) {
            __syncthreads();   // prior consumers of sU done
            if (isQ) {
                sQT2[ld4 + 0][lrow] = pack2(pf.x, pf.x);
                sQT2[ld4 + 1][lrow] = pack2(pf.y, pf.y);
                sQT2[ld4 + 2][lrow] = pack2(pf.z, pf.z);
                sQT2[ld4 + 3][lrow] = pack2(pf.w, pf.w);
            } else {
                sKT[ld4 + 0][lrow] = pf.x;
                sKT[ld4 + 1][lrow] = pf.y;
                sKT[ld4 + 2][lrow] = pf.z;
                sKT[ld4 + 3][lrow] = pf.w;
            }
            __syncthreads();
            if (c < 31) {  // software-pipelined prefetch of next chunk
                const float* src = (isQ ? gQrow : gKtile) + (c + 1) * 16;
                pf = *(const float4*)src;
            }
#pragma unroll
            for (int d = 0; d < 16; d++) {
                ulonglong2 q = *(const ulonglong2*)&sQT2[d][2 * ty];
                ulonglong2 k = *(const ulonglong2*)&sKT[d][4 * tx];
                a00 = fma2(q.x, k.x, a00);
                a01 = fma2(q.x, k.y, a01);
                a10 = fma2(q.y, k.x, a10);
                a11 = fma2(q.y, k.y, a11);
            }
        }
        // write scaled scores to sP
        {
            const float rs = 0.044194173824159216f;  // 1/sqrt(512)
            float s00, s01, s02, s03, s10, s11, s12, s13;
            unpack2(a00, s00, s01); unpack2(a01, s02, s03);
            unpack2(a10, s10, s11); unpack2(a11, s12, s13);
            *(float4*)&sP[2 * ty][4 * tx] =
                make_float4(s00 * rs, s01 * rs, s02 * rs, s03 * rs);
            *(float4*)&sP[2 * ty + 1][4 * tx] =
                make_float4(s10 * rs, s11 * rs, s12 * rs, s13 * rs);
        }
        __syncthreads();

        // ================= online softmax (8 threads per row) ==============
        {
            const int r = m_o, j = sg;
            const int gb = kt * 64 + j;
            float v[8];
            bool ok[8];
            float mm = -INFINITY;
#pragma unroll
            for (int k2 = 0; k2 < 8; k2++) {
                float x = sP[r][j + 8 * k2];
                ok[k2] = (gb + 8 * k2) < L;
                v[k2] = ok[k2] ? x : -INFINITY;
                mm = fmaxf(mm, v[k2]);
            }
            mm = fmaxf(mm, __shfl_xor_sync(0xffffffffu, mm, 4));
            mm = fmaxf(mm, __shfl_xor_sync(0xffffffffu, mm, 2));
            mm = fmaxf(mm, __shfl_xor_sync(0xffffffffu, mm, 1));
            float mold = s_m[r];
            float nm = fmaxf(mold, mm);
            float lsum = 0.f;
#pragma unroll
            for (int k2 = 0; k2 < 8; k2++) {
                float p = ok[k2] ? __expf(v[k2] - nm) : 0.f;
                sP[r][j + 8 * k2] = p;
                lsum += p;
            }
            lsum += __shfl_xor_sync(0xffffffffu, lsum, 4);
            lsum += __shfl_xor_sync(0xffffffffu, lsum, 2);
            lsum += __shfl_xor_sync(0xffffffffu, lsum, 1);
            if (j == 0) {
                float corr = __expf(mold - nm);
                s_l[r] = s_l[r] * corr + lsum;
                s_m[r] = nm;
                s_c[r] = corr;
            }
        }
        __syncthreads();

        // rescale running O by corr
        {
            float corr = s_c[m_o];
            ull c2 = pack2(corr, corr);
#pragma unroll
            for (int i = 0; i < 32; i++) o2[i] = mul2_(o2[i], c2);
        }

        // ================= GEMM2: O[64][512] += P[64][64] * V[64][512] =====
        const int un = t >> 7;       // 0..3 (second pass handles 4..7)
        const int uu = t & 127;      // 16B-unit index within 512-float row
        const int usw = uu ^ ((uu >> 4) & 7);  // XOR swizzle (bank spread)
        for (int vc = 0; vc < 8; vc++) {
            __syncthreads();  // prior reads of sV done
            {
                const float* gV =
                    Vp + ((size_t)(b * KK + kt * 64 + vc * 8)) * DD;
#pragma unroll
                for (int h = 0; h < 2; h++) {
                    int n = un + 4 * h;
                    float4 val = *(const float4*)(gV + (size_t)n * DD + uu * 4);
                    *(float4*)&sV[n * DD + usw * 4] = val;
                }
            }
            __syncthreads();
#pragma unroll 2
            for (int n = 0; n < 8; n++) {
                float p = sP[m_o][vc * 8 + n];
                ull p2 = pack2(p, p);
                const float* vrow = &sV[n * DD];
#pragma unroll
                for (int i = 0; i < 16; i++) {
                    int us = (sg * 16 + i) ^ sg;   // matches store swizzle
                    ulonglong2 vv = *(const ulonglong2*)&vrow[us * 4];
                    o2[2 * i]     = fma2(p2, vv.x, o2[2 * i]);
                    o2[2 * i + 1] = fma2(p2, vv.y, o2[2 * i + 1]);
                }
            }
        }
    }  // tile loop

    // ================= finalize with analytic masked-tail ==================
    {
        float mr = s_m[m_o];
        float lr = s_l[m_o];
        float M  = fmaxf(mr, 0.f);
        float c  = __expf(mr - M);
        float w0 = __expf(-M);
        float denom = lr * c + (float)(KK - L) * w0;
        float inv = 1.f / denom;
        float* orow =
            out + ((size_t)(b * QQ + qbase + m_o)) * DD + sg * 64;
        const float* vt = &g_vtail[b][sg * 64];
#pragma unroll
        for (int i = 0; i < 16; i++) {
            float x0, x1, x2, x3;
            unpack2(o2[2 * i], x0, x1);
            unpack2(o2[2 * i + 1], x2, x3);
            float4 tv = *(const float4*)(vt + 4 * i);
            float4 r4;
            r4.x = (x0 * c + w0 * tv.x) * inv;
            r4.y = (x1 * c + w0 * tv.y) * inv;
            r4.z = (x2 * c + w0 * tv.z) * inv;
            r4.w = (x3 * c + w0 * tv.w) * inv;
            *(float4*)(orow + 4 * i) = r4;
        }
    }
}

// ---------------------------------------------------------------------------
extern "C" void kernel_launch(void* const* d_in, const int* in_sizes, int n_in,
                              void* d_out, int out_size) {
    const float* Q    = (const float*)d_in[0];
    const float* K    = (const float*)d_in[1];
    const float* V    = (const float*)d_in[2];
    const int*   lens = (const int*)d_in[3];
    float* out = (float*)d_out;

    vtail_partial_kernel<<<dim3(16, BB), 512>>>(V, lens);
    vtail_reduce_kernel<<<BB, 512>>>();
    attn_kernel<<<dim3(QQ / 64, BB), 512>>>(Q, K, V, lens, out);
}

// round 2
// speedup vs baseline: 1.3407x; 1.3407x over previous
#include <cuda_runtime.h>
#include <cuda_bf16.h>
#include <cstdint>

// ============================================================================
// DotProductAttention: B=8, Q=2048, K=2048, D=512, fp32.
// masked_softmax-with-0 semantics => flash over valid keys + analytic tail:
//   M = max(m,0); c = exp(m-M); w0 = exp(-M)
//   out = (o*c + w0*Vtail) / (l*c + (K-L)*w0),  Vtail = sum_{k>=L} V[k]
// fp32 math via packed fma.rn.f32x2 (FFMA2).
// R2: balanced grid, double-buffered smem pipelines, FMA-bound blocking.
// ============================================================================

#define BB   8
#define QQ   2048
#define KK   2048
#define DD   512

typedef unsigned long long ull;

__device__ __forceinline__ ull pack2(float x, float y) {
    ull r; asm("mov.b64 %0, {%1, %2};" : "=l"(r) : "f"(x), "f"(y)); return r;
}
__device__ __forceinline__ void unpack2(ull v, float& x, float& y) {
    asm("mov.b64 {%0, %1}, %2;" : "=f"(x), "=f"(y) : "l"(v));
}
__device__ __forceinline__ ull fma2(ull a, ull b, ull c) {
    ull d; asm("fma.rn.f32x2 %0, %1, %2, %3;" : "=l"(d) : "l"(a), "l"(b), "l"(c)); return d;
}
__device__ __forceinline__ ull mul2_(ull a, ull b) {
    ull d; asm("mul.rn.f32x2 %0, %1, %2;" : "=l"(d) : "l"(a), "l"(b)); return d;
}

__device__ __align__(16) float g_partial[BB][16][DD];
__device__ __align__(16) float g_vtail[BB][DD];

// ---------------------------------------------------------------------------
__global__ void vtail_partial_kernel(const float* __restrict__ V,
                                     const int* __restrict__ lens) {
    int s = blockIdx.x, b = blockIdx.y, d = threadIdx.x;
    int L = lens[b]; L = L < 1 ? 1 : (L > KK ? KK : L);
    int k0 = s * 128, k1 = k0 + 128;
    int ks = k0 < L ? L : k0;
    float a = 0.f;
    const float* vp = V + ((size_t)b * KK) * DD + d;
    for (int k = ks; k < k1; k++) a += vp[(size_t)k * DD];
    g_partial[b][s][d] = a;
}

__global__ void vtail_reduce_kernel() {
    int b = blockIdx.x, d = threadIdx.x;
    float a = 0.f;
#pragma unroll
    for (int s = 0; s < 16; s++) a += g_partial[b][s][d];
    g_vtail[b][d] = a;
}

// ---------------------------------------------------------------------------
// Main kernel. 1-D grid of 256 CTAs, batch-interleaved: b = bid&7.
// Tile: 64 q x 64 k. 512 threads, O in registers (64 f32/thread).
// ---------------------------------------------------------------------------
__global__ void __launch_bounds__(512, 1)
attn_kernel(const float* __restrict__ Qp, const float* __restrict__ Kp,
            const float* __restrict__ Vp, const int* __restrict__ lens,
            float* __restrict__ out) {
    const int bid   = blockIdx.x;
    const int b     = bid & 7;
    const int qbase = (bid >> 3) << 6;
    const int t     = threadIdx.x;

    // ---- shared memory ----------------------------------------------------
    __shared__ __align__(16) float sP[64][68];          // 17408 B
    __shared__ float s_m[64], s_l[64], s_c[64];         //   768 B
    __shared__ __align__(16) unsigned char sU[25600];   // union region
    // GEMM1 staging (double buffered):
    //   qT[buf][d][r]  : Q^T chunk, 16 x 68 floats    (2 x 4352 B)
    //   kD[buf][d][r]  : dup-packed K^T chunk, 16x66 ull (2 x 8448 B)
    float (*qT)[16][68] = (float(*)[16][68])sU;
    ull   (*kD)[16][66] = (ull(*)[16][66])(sU + 8704);
    // GEMM2 staging (double buffered): sV[buf][4 rows][512 floats] swizzled
    float* sV = (float*)sU;                              // 2 x 8192 B

    int L = lens[b]; L = L < 1 ? 1 : (L > KK ? KK : L);
    const int nt = (L + 63) >> 6;

    // GEMM1 compute roles: 4q x 2k per thread
    const int ty = t >> 5;      // 0..15 : q rows 4ty..4ty+3
    const int tx = t & 31;      // 0..31 : k cols 2tx, 2tx+1

    // loader roles (GEMM1): threads [0,256) Q, [256,512) K
    const bool isQ = t < 256;
    const int lr = (t & 255) >> 2;   // row 0..63
    const int lc = (t & 3) << 2;     // d offset {0,4,8,12}
    const float* gQrow = Qp + ((size_t)(b * QQ + qbase + lr)) * DD + lc;

    // softmax roles
    const int m_o = t >> 3;     // row 0..63
    const int sg  = t & 7;      // 0..7

    // GEMM2 roles: 2 rows x 32 cols per thread
    const int m2 = t >> 4;      // 0..31 : rows 2m2, 2m2+1
    const int cs = t & 15;      // col segment: floats [32cs, 32cs+32)
    // V loader role
    const int vr = t >> 7;      // 0..3
    const int vu = t & 127;     // 16B unit within row
    const int vs = vu ^ ((vu >> 3) & 7);   // swizzled store unit

    if (t < 64) { s_m[t] = -INFINITY; s_l[t] = 0.f; }

    ull o2[32];
#pragma unroll
    for (int i = 0; i < 32; i++) o2[i] = 0ull;
    __syncthreads();

#pragma unroll 1
    for (int kt = 0; kt < nt; kt++) {
        const float* gKrow =
            Kp + ((size_t)(b * KK + (kt << 6) + lr)) * DD + lc;
        const float* gsrc = isQ ? gQrow : gKrow;

        // ============== GEMM1: S = Q * K^T (double-buffered d-chunks) ======
        ull a0 = 0, a1 = 0, a2 = 0, a3 = 0;
        {
            // prologue: chunk 0
            float4 pf = *(const float4*)gsrc;
            if (isQ) {
                float* d0 = &qT[0][lc][lr];
                d0[0] = pf.x; d0[68] = pf.y; d0[136] = pf.z; d0[204] = pf.w;
            } else {
                ull* d0 = &kD[0][lc][lr];
                d0[0] = pack2(pf.x, pf.x); d0[66]  = pack2(pf.y, pf.y);
                d0[132] = pack2(pf.z, pf.z); d0[198] = pack2(pf.w, pf.w);
            }
            __syncthreads();
#pragma unroll 1
            for (int c = 0; c < 32; c++) {
                if (c < 31) pf = *(const float4*)(gsrc + (c + 1) * 16);
                const int cb = c & 1;
#pragma unroll
                for (int d = 0; d < 16; d++) {
                    float4 qv = *(const float4*)&qT[cb][d][4 * ty];
                    ulonglong2 kv = *(const ulonglong2*)&kD[cb][d][2 * tx];
                    ull qp01 = pack2(qv.x, qv.y);
                    ull qp23 = pack2(qv.z, qv.w);
                    a0 = fma2(qp01, kv.x, a0);
                    a1 = fma2(qp23, kv.x, a1);
                    a2 = fma2(qp01, kv.y, a2);
                    a3 = fma2(qp23, kv.y, a3);
                }
                if (c < 31) {
                    const int nb = cb ^ 1;
                    if (isQ) {
                        float* d0 = &qT[nb][lc][lr];
                        d0[0] = pf.x; d0[68] = pf.y; d0[136] = pf.z; d0[204] = pf.w;
                    } else {
                        ull* d0 = &kD[nb][lc][lr];
                        d0[0] = pack2(pf.x, pf.x); d0[66]  = pack2(pf.y, pf.y);
                        d0[132] = pack2(pf.z, pf.z); d0[198] = pack2(pf.w, pf.w);
                    }
                }
                __syncthreads();
            }
        }
        // write scaled scores: rows 4ty+p, cols 2tx,2tx+1
        {
            const float rs = 0.044194173824159216f;  // 1/sqrt(512)
            float x0, y0, x1, y1;
            unpack2(a0, x0, y0); unpack2(a2, x1, y1);
            *(float2*)&sP[4 * ty + 0][2 * tx] = make_float2(x0 * rs, x1 * rs);
            *(float2*)&sP[4 * ty + 1][2 * tx] = make_float2(y0 * rs, y1 * rs);
            unpack2(a1, x0, y0); unpack2(a3, x1, y1);
            *(float2*)&sP[4 * ty + 2][2 * tx] = make_float2(x0 * rs, x1 * rs);
            *(float2*)&sP[4 * ty + 3][2 * tx] = make_float2(y0 * rs, y1 * rs);
        }
        __syncthreads();

        // ============== online softmax (8 threads per row) ==================
        {
            const int r = m_o;
            const int gb = (kt << 6) + sg;
            float mm = -INFINITY;
#pragma unroll
            for (int k2 = 0; k2 < 8; k2++) {
                float x = sP[r][sg + 8 * k2];
                x = (gb + 8 * k2) < L ? x : -INFINITY;
                mm = fmaxf(mm, x);
            }
            mm = fmaxf(mm, __shfl_xor_sync(0xffffffffu, mm, 4));
            mm = fmaxf(mm, __shfl_xor_sync(0xffffffffu, mm, 2));
            mm = fmaxf(mm, __shfl_xor_sync(0xffffffffu, mm, 1));
            float mold = s_m[r];
            float nm = fmaxf(mold, mm);
            float lsum = 0.f;
#pragma unroll
            for (int k2 = 0; k2 < 8; k2++) {
                float x = sP[r][sg + 8 * k2];
                float p = (gb + 8 * k2) < L ? __expf(x - nm) : 0.f;
                sP[r][sg + 8 * k2] = p;
                lsum += p;
            }
            lsum += __shfl_xor_sync(0xffffffffu, lsum, 4);
            lsum += __shfl_xor_sync(0xffffffffu, lsum, 2);
            lsum += __shfl_xor_sync(0xffffffffu, lsum, 1);
            if (sg == 0) {
                float corr = __expf(mold - nm);
                s_l[r] = s_l[r] * corr + lsum;
                s_m[r] = nm;
                s_c[r] = corr;
            }
        }
        __syncthreads();

        // ============== GEMM2: O += P * V (double-buffered 4-row chunks) ===
        {
            // rescale running O
            ull c0 = pack2(s_c[2 * m2], s_c[2 * m2]);
            ull c1 = pack2(s_c[2 * m2 + 1], s_c[2 * m2 + 1]);
#pragma unroll
            for (int i = 0; i < 16; i++) o2[i] = mul2_(o2[i], c0);
#pragma unroll
            for (int i = 0; i < 16; i++) o2[16 + i] = mul2_(o2[16 + i], c1);

            const float* gV0 =
                Vp + ((size_t)(b * KK + (kt << 6) + vr)) * DD + vu * 4;
            // prologue: V rows 0..3
            float4 pv = *(const float4*)gV0;
            *(float4*)&sV[vr * 512 + vs * 4] = pv;
            __syncthreads();
#pragma unroll 1
            for (int vc = 0; vc < 16; vc++) {
                if (vc < 15)
                    pv = *(const float4*)(gV0 + (size_t)(vc + 1) * 4 * DD);
                const float* sVb = sV + (vc & 1) * 2048;
#pragma unroll
                for (int j = 0; j < 4; j++) {
                    const int nn = vc * 4 + j;
                    float p0 = sP[2 * m2][nn];
                    float p1 = sP[2 * m2 + 1][nn];
                    ull p0d = pack2(p0, p0);
                    ull p1d = pack2(p1, p1);
                    const float* vrow = sVb + j * 512;
#pragma unroll
                    for (int u8 = 0; u8 < 8; u8++) {
                        const int su = (cs * 8 + u8) ^ (cs & 7);
                        ulonglong2 vv = *(const ulonglong2*)&vrow[su * 4];
                        o2[2 * u8]      = fma2(p0d, vv.x, o2[2 * u8]);
                        o2[2 * u8 + 1]  = fma2(p0d, vv.y, o2[2 * u8 + 1]);
                        o2[16 + 2 * u8]     = fma2(p1d, vv.x, o2[16 + 2 * u8]);
                        o2[16 + 2 * u8 + 1] = fma2(p1d, vv.y, o2[16 + 2 * u8 + 1]);
                    }
                }
                if (vc < 15)
                    *(float4*)&sV[((vc + 1) & 1) * 2048 + vr * 512 + vs * 4] = pv;
                __syncthreads();
            }
        }
    }  // tile loop

    // ============== finalize with analytic masked-tail ======================
    {
#pragma unroll
        for (int p = 0; p < 2; p++) {
            const int r = 2 * m2 + p;
            float mr = s_m[r];
            float lr_ = s_l[r];
            float M  = fmaxf(mr, 0.f);
            float c  = __expf(mr - M);
            float w0 = __expf(-M);
            float inv = 1.f / (lr_ * c + (float)(KK - L) * w0);
            float* orow = out + ((size_t)(b * QQ + qbase + r)) * DD + cs * 32;
            const float* vt = &g_vtail[b][cs * 32];
#pragma unroll
            for (int i = 0; i < 8; i++) {
                float x0, x1, x2, x3;
                unpack2(o2[p * 16 + 2 * i], x0, x1);
                unpack2(o2[p * 16 + 2 * i + 1], x2, x3);
                float4 tv = *(const float4*)(vt + 4 * i);
                float4 r4;
                r4.x = (x0 * c + w0 * tv.x) * inv;
                r4.y = (x1 * c + w0 * tv.y) * inv;
                r4.z = (x2 * c + w0 * tv.z) * inv;
                r4.w = (x3 * c + w0 * tv.w) * inv;
                *(float4*)(orow + 4 * i) = r4;
            }
        }
    }
}

// ---------------------------------------------------------------------------
extern "C" void kernel_launch(void* const* d_in, const int* in_sizes, int n_in,
                              void* d_out, int out_size) {
    const float* Q    = (const float*)d_in[0];
    const float* K    = (const float*)d_in[1];
    const float* V    = (const float*)d_in[2];
    const int*   lens = (const int*)d_in[3];
    float* out = (float*)d_out;

    vtail_partial_kernel<<<dim3(16, BB), 512>>>(V, lens);
    vtail_reduce_kernel<<<BB, 512>>>();
    attn_kernel<<<256, 512>>>(Q, K, V, lens, out);
}

// round 4
// speedup vs baseline: 1.5780x; 1.1770x over previous
#include <cuda_runtime.h>
#include <cuda_bf16.h>
#include <cstdint>

// ============================================================================
// DotProductAttention: B=8, Q=2048, K=2048, D=512, fp32.
// masked_softmax-with-0 semantics => flash over valid keys + analytic tail:
//   M = max(m,0); c = exp(m-M); w0 = exp(-M)
//   out = (o*c + w0*Vtail) / (l*c + (K-L)*w0),  Vtail = sum_{k>=L} V[k]
// R4: R3 design with K-loader depth-offset fix (gK+8, was gK+8*DD).
// 32q x 128k tiles, 256 thr, 2 CTAs/SM, conflict-free LDS, FFMA2 math.
// ============================================================================

#define BB   8
#define QQ   2048
#define KK   2048
#define DD   512
#define MT   32
#define NT   128

typedef unsigned long long ull;

__device__ __forceinline__ ull pack2(float x, float y) {
    ull r; asm("mov.b64 %0, {%1, %2};" : "=l"(r) : "f"(x), "f"(y)); return r;
}
__device__ __forceinline__ void unpack2(ull v, float& x, float& y) {
    asm("mov.b64 {%0, %1}, %2;" : "=f"(x), "=f"(y) : "l"(v));
}
__device__ __forceinline__ ull fma2(ull a, ull b, ull c) {
    ull d; asm("fma.rn.f32x2 %0, %1, %2, %3;" : "=l"(d) : "l"(a), "l"(b), "l"(c)); return d;
}
__device__ __forceinline__ ull mul2_(ull a, ull b) {
    ull d; asm("mul.rn.f32x2 %0, %1, %2;" : "=l"(d) : "l"(a), "l"(b)); return d;
}

__device__ __align__(16) float g_partial[BB][16][DD];

// ---------------------------------------------------------------------------
__global__ void vtail_partial_kernel(const float* __restrict__ V,
                                     const int* __restrict__ lens) {
    int s = blockIdx.x, b = blockIdx.y, d = threadIdx.x;
    int L = lens[b]; L = L < 1 ? 1 : (L > KK ? KK : L);
    int k0 = s * 128, k1 = k0 + 128;
    int ks = k0 < L ? L : k0;
    float a = 0.f;
    const float* vp = V + ((size_t)b * KK) * DD + d;
    for (int k = ks; k < k1; k++) a += vp[(size_t)k * DD];
    g_partial[b][s][d] = a;
}

// ---------------------------------------------------------------------------
// smem layout (bytes):
//   [0, 16896)      sP[32][132] floats
//   [16896,17024)   s_m[32]
//   [17024,17152)   s_l[32]
//   [17152,17280)   s_c[32]
//   [17280,19328)   s_vt[512]
//   [19328, ...)    U: gemm1 staging (qT[2][16][36] f + kD[2][16][128] ull)
//                      OR sV[2][4][512] f
#define SM_P    0
#define SM_M    16896
#define SM_L    17024
#define SM_C    17152
#define SM_VT   17280
#define SM_U    19328
#define SM_QT   (SM_U)
#define SM_KD   (SM_U + 4608)
#define SM_SV   (SM_U)
#define SMEM_BYTES (SM_U + 4608 + 32768)   // 56704

__global__ void __launch_bounds__(256, 2)
attn_kernel(const float* __restrict__ Qp, const float* __restrict__ Kp,
            const float* __restrict__ Vp, const int* __restrict__ lens,
            float* __restrict__ out) {
    extern __shared__ __align__(16) unsigned char dsm[];
    float (*sP)[132]     = (float(*)[132])(dsm + SM_P);
    float* s_m           = (float*)(dsm + SM_M);
    float* s_l           = (float*)(dsm + SM_L);
    float* s_c           = (float*)(dsm + SM_C);
    float* s_vt          = (float*)(dsm + SM_VT);
    float (*qT)[16][36]  = (float(*)[16][36])(dsm + SM_QT);
    ull   (*kD)[16][128] = (ull(*)[16][128])(dsm + SM_KD);
    float (*sV)[4][512]  = (float(*)[4][512])(dsm + SM_SV);

    const int bid   = blockIdx.x;
    const int b     = bid & 7;
    const int qbase = (bid >> 3) * MT;
    const int t     = threadIdx.x;
    const int wid   = t >> 5;        // 0..7  (row group: rows 4*wid..4*wid+3)
    const int lane  = t & 31;

    int L = lens[b]; L = L < 1 ? 1 : (L > KK ? KK : L);
    const int nt = (L + NT - 1) / NT;

    // loader roles
    const int qlr = t & 31;          // Q row (t<128 only)
    const int qld = (t >> 5) << 2;   // Q d-offset 0/4/8/12 (t<128)
    const int klc = t & 127;         // K row within tile
    const int kld = (t >> 7) << 2;   // K d-offset 0/4 (second half at +8)
    // softmax roles
    const int sr = t >> 3, sg = t & 7;

    // init stats + vtail reduce into smem
    if (t < 32) { s_m[t] = -INFINITY; s_l[t] = 0.f; }
#pragma unroll
    for (int h = 0; h < 2; h++) {
        int d = t + 256 * h;
        float a = 0.f;
#pragma unroll
        for (int s = 0; s < 16; s++) a += g_partial[b][s][d];
        s_vt[d] = a;
    }

    ull o2[4][4][2];
#pragma unroll
    for (int i = 0; i < 4; i++)
#pragma unroll
        for (int s = 0; s < 4; s++) { o2[i][s][0] = 0; o2[i][s][1] = 0; }

    __syncthreads();

#pragma unroll 1
    for (int kt = 0; kt < nt; kt++) {
        const float* gQ = Qp + ((size_t)(b * QQ + qbase + qlr)) * DD + qld;
        const float* gK = Kp + ((size_t)(b * KK + kt * NT + klc)) * DD + kld;

        // ================= GEMM1: S[32][128] = Q * K^T ======================
        ull a2[2][4];
#pragma unroll
        for (int i = 0; i < 2; i++)
#pragma unroll
            for (int j = 0; j < 4; j++) a2[i][j] = 0;
        {
            float4 pk0 = *(const float4*)gK;
            float4 pk1 = *(const float4*)(gK + 8);   // depth kld+8 (FIXED)
            float4 pq;
            if (t < 128) pq = *(const float4*)gQ;
            // store chunk 0 into buf 0
            {
                ull* kp = &kD[0][kld][klc];
                kp[0]   = pack2(pk0.x, pk0.x);
                kp[128] = pack2(pk0.y, pk0.y);
                kp[256] = pack2(pk0.z, pk0.z);
                kp[384] = pack2(pk0.w, pk0.w);
                ull* kp2 = &kD[0][kld + 8][klc];
                kp2[0]   = pack2(pk1.x, pk1.x);
                kp2[128] = pack2(pk1.y, pk1.y);
                kp2[256] = pack2(pk1.z, pk1.z);
                kp2[384] = pack2(pk1.w, pk1.w);
                if (t < 128) {
                    float* qp = &qT[0][qld][qlr];
                    qp[0] = pq.x; qp[36] = pq.y; qp[72] = pq.z; qp[108] = pq.w;
                }
            }
            __syncthreads();
#pragma unroll 1
            for (int c = 0; c < 32; c++) {
                if (c < 31) {
                    pk0 = *(const float4*)(gK + (c + 1) * 16);
                    pk1 = *(const float4*)(gK + 8 + (c + 1) * 16);  // FIXED
                    if (t < 128) pq = *(const float4*)(gQ + (c + 1) * 16);
                }
                const int cb = c & 1;
#pragma unroll
                for (int d = 0; d < 16; d++) {
                    float4 qv = *(const float4*)&qT[cb][d][4 * wid];
                    ulonglong2 kv1 = *(const ulonglong2*)&kD[cb][d][2 * lane];
                    ulonglong2 kv2 = *(const ulonglong2*)&kD[cb][d][64 + 2 * lane];
                    ull qp0 = pack2(qv.x, qv.y);
                    ull qp1 = pack2(qv.z, qv.w);
                    a2[0][0] = fma2(qp0, kv1.x, a2[0][0]);
                    a2[0][1] = fma2(qp0, kv1.y, a2[0][1]);
                    a2[0][2] = fma2(qp0, kv2.x, a2[0][2]);
                    a2[0][3] = fma2(qp0, kv2.y, a2[0][3]);
                    a2[1][0] = fma2(qp1, kv1.x, a2[1][0]);
                    a2[1][1] = fma2(qp1, kv1.y, a2[1][1]);
                    a2[1][2] = fma2(qp1, kv2.x, a2[1][2]);
                    a2[1][3] = fma2(qp1, kv2.y, a2[1][3]);
                }
                if (c < 31) {
                    const int nb = (c + 1) & 1;
                    ull* kp = &kD[nb][kld][klc];
                    kp[0]   = pack2(pk0.x, pk0.x);
                    kp[128] = pack2(pk0.y, pk0.y);
                    kp[256] = pack2(pk0.z, pk0.z);
                    kp[384] = pack2(pk0.w, pk0.w);
                    ull* kp2 = &kD[nb][kld + 8][klc];
                    kp2[0]   = pack2(pk1.x, pk1.x);
                    kp2[128] = pack2(pk1.y, pk1.y);
                    kp2[256] = pack2(pk1.z, pk1.z);
                    kp2[384] = pack2(pk1.w, pk1.w);
                    if (t < 128) {
                        float* qp = &qT[nb][qld][qlr];
                        qp[0] = pq.x; qp[36] = pq.y; qp[72] = pq.z; qp[108] = pq.w;
                    }
                }
                __syncthreads();
            }
        }
        // write scaled scores
        {
            const float rs = 0.044194173824159216f;  // 1/sqrt(512)
#pragma unroll
            for (int i = 0; i < 2; i++) {
                const int r0 = 4 * wid + 2 * i;
                float x0, y0, x1, y1;
                unpack2(a2[i][0], x0, y0);
                unpack2(a2[i][1], x1, y1);
                *(float2*)&sP[r0][2 * lane]     = make_float2(x0 * rs, x1 * rs);
                *(float2*)&sP[r0 + 1][2 * lane] = make_float2(y0 * rs, y1 * rs);
                unpack2(a2[i][2], x0, y0);
                unpack2(a2[i][3], x1, y1);
                *(float2*)&sP[r0][64 + 2 * lane]     = make_float2(x0 * rs, x1 * rs);
                *(float2*)&sP[r0 + 1][64 + 2 * lane] = make_float2(y0 * rs, y1 * rs);
            }
        }
        __syncthreads();

        // ================= online softmax (8 threads/row, 16 cols each) ====
        {
            const int gb = kt * NT + sg;
            float mm = -INFINITY;
#pragma unroll
            for (int k2 = 0; k2 < 16; k2++) {
                float x = sP[sr][sg + 8 * k2];
                x = (gb + 8 * k2) < L ? x : -INFINITY;
                mm = fmaxf(mm, x);
            }
            mm = fmaxf(mm, __shfl_xor_sync(0xffffffffu, mm, 4));
            mm = fmaxf(mm, __shfl_xor_sync(0xffffffffu, mm, 2));
            mm = fmaxf(mm, __shfl_xor_sync(0xffffffffu, mm, 1));
            float mold = s_m[sr];
            float nm = fmaxf(mold, mm);
            float lsum = 0.f;
#pragma unroll
            for (int k2 = 0; k2 < 16; k2++) {
                float x = sP[sr][sg + 8 * k2];
                float p = (gb + 8 * k2) < L ? __expf(x - nm) : 0.f;
                sP[sr][sg + 8 * k2] = p;
                lsum += p;
            }
            lsum += __shfl_xor_sync(0xffffffffu, lsum, 4);
            lsum += __shfl_xor_sync(0xffffffffu, lsum, 2);
            lsum += __shfl_xor_sync(0xffffffffu, lsum, 1);
            if (sg == 0) {
                float corr = __expf(mold - nm);
                s_l[sr] = s_l[sr] * corr + lsum;
                s_m[sr] = nm;
                s_c[sr] = corr;
            }
        }
        __syncthreads();

        // ================= GEMM2: O[32][512] += P[32][128] * V[128][512] ===
        {
            // rescale running O
#pragma unroll
            for (int i = 0; i < 4; i++) {
                float cc = s_c[4 * wid + i];
                ull c2 = pack2(cc, cc);
#pragma unroll
                for (int s = 0; s < 4; s++) {
                    o2[i][s][0] = mul2_(o2[i][s][0], c2);
                    o2[i][s][1] = mul2_(o2[i][s][1], c2);
                }
            }

            const float* gV = Vp + ((size_t)(b * KK + kt * NT)) * DD;
            const int r0 = t >> 7,         u0 = t & 127;
            const int r1 = (t + 256) >> 7, u1 = t & 127;
            float4 pv0 = *(const float4*)(gV + (size_t)r0 * DD + 4 * u0);
            float4 pv1 = *(const float4*)(gV + (size_t)r1 * DD + 4 * u1);
            *(float4*)&sV[0][r0][4 * u0] = pv0;
            *(float4*)&sV[0][r1][4 * u1] = pv1;
            __syncthreads();
#pragma unroll 1
            for (int vc = 0; vc < 32; vc++) {
                if (vc < 31) {
                    const float* gVn = gV + (size_t)((vc + 1) * 4) * DD;
                    pv0 = *(const float4*)(gVn + (size_t)r0 * DD + 4 * u0);
                    pv1 = *(const float4*)(gVn + (size_t)r1 * DD + 4 * u1);
                }
                const int vb = vc & 1;
#pragma unroll
                for (int j = 0; j < 4; j++) {
                    const int n = vc * 4 + j;
                    ull p2[4];
#pragma unroll
                    for (int i = 0; i < 4; i++) {
                        float p = sP[4 * wid + i][n];
                        p2[i] = pack2(p, p);
                    }
#pragma unroll
                    for (int s = 0; s < 4; s++) {
                        ulonglong2 vv =
                            *(const ulonglong2*)&sV[vb][j][4 * lane + 128 * s];
#pragma unroll
                        for (int i = 0; i < 4; i++) {
                            o2[i][s][0] = fma2(p2[i], vv.x, o2[i][s][0]);
                            o2[i][s][1] = fma2(p2[i], vv.y, o2[i][s][1]);
                        }
                    }
                }
                if (vc < 31) {
                    const int nb = (vc + 1) & 1;
                    *(float4*)&sV[nb][r0][4 * u0] = pv0;
                    *(float4*)&sV[nb][r1][4 * u1] = pv1;
                }
                __syncthreads();
            }
        }
    }  // tile loop

    // ================= finalize with analytic masked-tail ===================
#pragma unroll
    for (int i = 0; i < 4; i++) {
        const int r = 4 * wid + i;
        float mr = s_m[r];
        float lr_ = s_l[r];
        float M  = fmaxf(mr, 0.f);
        float c  = __expf(mr - M);
        float w0 = __expf(-M);
        float inv = 1.f / (lr_ * c + (float)(KK - L) * w0);
        float* orow = out + ((size_t)(b * QQ + qbase + r)) * DD;
#pragma unroll
        for (int s = 0; s < 4; s++) {
            float4 tv = *(const float4*)&s_vt[4 * lane + 128 * s];
            float x0, x1, x2, x3;
            unpack2(o2[i][s][0], x0, x1);
            unpack2(o2[i][s][1], x2, x3);
            float4 r4;
            r4.x = (x0 * c + w0 * tv.x) * inv;
            r4.y = (x1 * c + w0 * tv.y) * inv;
            r4.z = (x2 * c + w0 * tv.z) * inv;
            r4.w = (x3 * c + w0 * tv.w) * inv;
            *(float4*)(orow + 4 * lane + 128 * s) = r4;
        }
    }
}

// ---------------------------------------------------------------------------
extern "C" void kernel_launch(void* const* d_in, const int* in_sizes, int n_in,
                              void* d_out, int out_size) {
    const float* Q    = (const float*)d_in[0];
    const float* K    = (const float*)d_in[1];
    const float* V    = (const float*)d_in[2];
    const int*   lens = (const int*)d_in[3];
    float* out = (float*)d_out;

    cudaFuncSetAttribute(attn_kernel,
                         cudaFuncAttributeMaxDynamicSharedMemorySize,
                         SMEM_BYTES);

    vtail_partial_kernel<<<dim3(16, BB), 512>>>(V, lens);
    attn_kernel<<<512, 256, SMEM_BYTES>>>(Q, K, V, lens, out);
}

// round 5
// speedup vs baseline: 1.8306x; 1.1601x over previous
#include <cuda_runtime.h>
#include <cuda_bf16.h>
#include <cstdint>

// ============================================================================
// DotProductAttention: B=8, Q=2048, K=2048, D=512, fp32.
// masked_softmax-with-0 => flash over valid keys + analytic tail:
//   M = max(m,0); c = exp(m-M); w0 = exp(-M)
//   out = (o*c + w0*Vtail) / (l*c + (K-L)*w0),  Vtail = sum_{k>=L} V[k]
// R5: NT=256, GEMM1 as 2 k-half passes (8q x 2k, K dup in registers),
//     GEMM2 8x8 thread tile. LDS:FMA rebalanced from 2.8:1 to ~1:1.
// ============================================================================

#define BB   8
#define QQ   2048
#define KK   2048
#define DD   512
#define MT   32
#define NT   256

typedef unsigned long long ull;

__device__ __forceinline__ ull pack2(float x, float y) {
    ull r; asm("mov.b64 %0, {%1, %2};" : "=l"(r) : "f"(x), "f"(y)); return r;
}
__device__ __forceinline__ void unpack2(ull v, float& x, float& y) {
    asm("mov.b64 {%0, %1}, %2;" : "=f"(x), "=f"(y) : "l"(v));
}
__device__ __forceinline__ ull fma2(ull a, ull b, ull c) {
    ull d; asm("fma.rn.f32x2 %0, %1, %2, %3;" : "=l"(d) : "l"(a), "l"(b), "l"(c)); return d;
}
__device__ __forceinline__ ull mul2_(ull a, ull b) {
    ull d; asm("mul.rn.f32x2 %0, %1, %2;" : "=l"(d) : "l"(a), "l"(b)); return d;
}

__device__ __align__(16) float g_partial[BB][16][DD];

// ---------------------------------------------------------------------------
__global__ void vtail_partial_kernel(const float* __restrict__ V,
                                     const int* __restrict__ lens) {
    int s = blockIdx.x, b = blockIdx.y, d = threadIdx.x;
    int L = lens[b]; L = L < 1 ? 1 : (L > KK ? KK : L);
    int k0 = s * 128, k1 = k0 + 128;
    int ks = k0 < L ? L : k0;
    float a = 0.f;
    const float* vp = V + ((size_t)b * KK) * DD + d;
    for (int k = ks; k < k1; k++) a += vp[(size_t)k * DD];
    g_partial[b][s][d] = a;
}

// ---------------------------------------------------------------------------
// smem layout (bytes):
//   sP[32][260]            0      .. 33280
//   s_m[32]                33280
//   s_l[32]                33408
//   s_c[32]                33536
//   s_vt[512]              33664  .. 35712
//   U (union):             35712
//     qT[2][16][36] f      35712 (4608)
//     kN[2][16][132] f     40320 (16896)
//     -- or --  sV[2][4][512] f (16384)
#define SM_P    0
#define SM_M    33280
#define SM_L    33408
#define SM_C    33536
#define SM_VT   33664
#define SM_U    35712
#define SM_QT   (SM_U)
#define SM_KN   (SM_U + 4608)
#define SM_SV   (SM_U)
#define SMEM_BYTES (SM_U + 4608 + 16896)   // 57216

__global__ void __launch_bounds__(256, 2)
attn_kernel(const float* __restrict__ Qp, const float* __restrict__ Kp,
            const float* __restrict__ Vp, const int* __restrict__ lens,
            float* __restrict__ out) {
    extern __shared__ __align__(16) unsigned char dsm[];
    float (*sP)[260]     = (float(*)[260])(dsm + SM_P);
    float* s_m           = (float*)(dsm + SM_M);
    float* s_l           = (float*)(dsm + SM_L);
    float* s_c           = (float*)(dsm + SM_C);
    float* s_vt          = (float*)(dsm + SM_VT);
    float (*qT)[16][36]  = (float(*)[16][36])(dsm + SM_QT);
    float (*kN)[16][132] = (float(*)[16][132])(dsm + SM_KN);
    float (*sV)[4][512]  = (float(*)[4][512])(dsm + SM_SV);

    const int bid   = blockIdx.x;
    const int b     = bid & 7;
    const int qbase = (bid >> 3) * MT;
    const int t     = threadIdx.x;

    int L = lens[b]; L = L < 1 ? 1 : (L > KK ? KK : L);
    const int nt = (L + NT - 1) / NT;

    // GEMM1 compute roles: 8q x 2k
    const int qg = t >> 6;          // 0..3 : q rows 8qg..8qg+7
    const int kk = t & 63;          // k cols 2kk, 2kk+1 (within 128-half)
    // K loader: 128 rows x 16 d per chunk
    const int klr  = t & 127;       // K row within half
    const int kldh = (t >> 7) * 8;  // d sub-offset 0 or 8
    // Q loader (t < 128): 32 rows x 16 d per chunk
    const int qlr  = t & 31;
    const int qldh = ((t & 127) >> 5) * 4;  // 0,4,8,12
    // softmax roles
    const int sr = t >> 3, sg = t & 7;
    // GEMM2 roles: 8 rows x 8 cols (cols 4cg..+3 and 4cg+256..+259)
    const int rg = t >> 6;
    const int cg = t & 63;
    // V loader
    const int vr0 = t >> 7;         // 0..1 (also loads row vr0+2)
    const int vu  = t & 127;

    // init stats + vtail reduce into smem
    if (t < 32) { s_m[t] = -INFINITY; s_l[t] = 0.f; }
#pragma unroll
    for (int h = 0; h < 2; h++) {
        int d = t + 256 * h;
        float a = 0.f;
#pragma unroll
        for (int s = 0; s < 16; s++) a += g_partial[b][s][d];
        s_vt[d] = a;
    }

    ull o2[8][2][2];
#pragma unroll
    for (int i = 0; i < 8; i++)
#pragma unroll
        for (int s = 0; s < 2; s++) { o2[i][s][0] = 0; o2[i][s][1] = 0; }

    __syncthreads();

#pragma unroll 1
    for (int kt = 0; kt < nt; kt++) {

        // ============== GEMM1: S[32][256], two 128-col passes ==============
#pragma unroll 1
        for (int h = 0; h < 2; h++) {
            const float* gK =
                Kp + ((size_t)(b * KK + kt * NT + h * 128 + klr)) * DD + kldh;
            const float* gQ =
                Qp + ((size_t)(b * QQ + qbase + qlr)) * DD + qldh;

            ull a2[4][2];
#pragma unroll
            for (int p = 0; p < 4; p++) { a2[p][0] = 0; a2[p][1] = 0; }

            // prologue chunk 0
            float4 pk0 = *(const float4*)gK;
            float4 pk1 = *(const float4*)(gK + 4);
            float4 pq;
            if (t < 128) pq = *(const float4*)gQ;
            {
                kN[0][kldh + 0][klr] = pk0.x;
                kN[0][kldh + 1][klr] = pk0.y;
                kN[0][kldh + 2][klr] = pk0.z;
                kN[0][kldh + 3][klr] = pk0.w;
                kN[0][kldh + 4][klr] = pk1.x;
                kN[0][kldh + 5][klr] = pk1.y;
                kN[0][kldh + 6][klr] = pk1.z;
                kN[0][kldh + 7][klr] = pk1.w;
                if (t < 128) {
                    qT[0][qldh + 0][qlr] = pq.x;
                    qT[0][qldh + 1][qlr] = pq.y;
                    qT[0][qldh + 2][qlr] = pq.z;
                    qT[0][qldh + 3][qlr] = pq.w;
                }
            }
            __syncthreads();
#pragma unroll 1
            for (int c = 0; c < 32; c++) {
                if (c < 31) {
                    pk0 = *(const float4*)(gK + (c + 1) * 16);
                    pk1 = *(const float4*)(gK + (c + 1) * 16 + 4);
                    if (t < 128) pq = *(const float4*)(gQ + (c + 1) * 16);
                }
                const int cb = c & 1;
#pragma unroll
                for (int d = 0; d < 16; d++) {
                    float4 qv0 = *(const float4*)&qT[cb][d][8 * qg];
                    float4 qv1 = *(const float4*)&qT[cb][d][8 * qg + 4];
                    float2 kv  = *(const float2*)&kN[cb][d][2 * kk];
                    ull kd0 = pack2(kv.x, kv.x);
                    ull kd1 = pack2(kv.y, kv.y);
                    ull qp0 = pack2(qv0.x, qv0.y);
                    ull qp1 = pack2(qv0.z, qv0.w);
                    ull qp2 = pack2(qv1.x, qv1.y);
                    ull qp3 = pack2(qv1.z, qv1.w);
                    a2[0][0] = fma2(qp0, kd0, a2[0][0]);
                    a2[0][1] = fma2(qp0, kd1, a2[0][1]);
                    a2[1][0] = fma2(qp1, kd0, a2[1][0]);
                    a2[1][1] = fma2(qp1, kd1, a2[1][1]);
                    a2[2][0] = fma2(qp2, kd0, a2[2][0]);
                    a2[2][1] = fma2(qp2, kd1, a2[2][1]);
                    a2[3][0] = fma2(qp3, kd0, a2[3][0]);
                    a2[3][1] = fma2(qp3, kd1, a2[3][1]);
                }
                if (c < 31) {
                    const int nb = (c + 1) & 1;
                    kN[nb][kldh + 0][klr] = pk0.x;
                    kN[nb][kldh + 1][klr] = pk0.y;
                    kN[nb][kldh + 2][klr] = pk0.z;
                    kN[nb][kldh + 3][klr] = pk0.w;
                    kN[nb][kldh + 4][klr] = pk1.x;
                    kN[nb][kldh + 5][klr] = pk1.y;
                    kN[nb][kldh + 6][klr] = pk1.z;
                    kN[nb][kldh + 7][klr] = pk1.w;
                    if (t < 128) {
                        qT[nb][qldh + 0][qlr] = pq.x;
                        qT[nb][qldh + 1][qlr] = pq.y;
                        qT[nb][qldh + 2][qlr] = pq.z;
                        qT[nb][qldh + 3][qlr] = pq.w;
                    }
                }
                __syncthreads();
            }
            // write scaled scores: rows 8qg+2p (+1), cols h*128 + 2kk (+1)
            {
                const float rs = 0.044194173824159216f;  // 1/sqrt(512)
                const int cbase = h * 128 + 2 * kk;
#pragma unroll
                for (int p = 0; p < 4; p++) {
                    float x0, y0, x1, y1;
                    unpack2(a2[p][0], x0, y0);  // (s[q2p][k0], s[q2p+1][k0])
                    unpack2(a2[p][1], x1, y1);
                    *(float2*)&sP[8 * qg + 2 * p][cbase] =
                        make_float2(x0 * rs, x1 * rs);
                    *(float2*)&sP[8 * qg + 2 * p + 1][cbase] =
                        make_float2(y0 * rs, y1 * rs);
                }
            }
        }
        __syncthreads();

        // ============== online softmax (8 threads/row, 32 cols each) =======
        {
            const int gb = kt * NT + sg;
            float mm = -INFINITY;
#pragma unroll
            for (int k2 = 0; k2 < 32; k2++) {
                float x = sP[sr][sg + 8 * k2];
                x = (gb + 8 * k2) < L ? x : -INFINITY;
                mm = fmaxf(mm, x);
            }
            mm = fmaxf(mm, __shfl_xor_sync(0xffffffffu, mm, 4));
            mm = fmaxf(mm, __shfl_xor_sync(0xffffffffu, mm, 2));
            mm = fmaxf(mm, __shfl_xor_sync(0xffffffffu, mm, 1));
            float mold = s_m[sr];
            float nm = fmaxf(mold, mm);
            float lsum = 0.f;
#pragma unroll
            for (int k2 = 0; k2 < 32; k2++) {
                float x = sP[sr][sg + 8 * k2];
                float p = (gb + 8 * k2) < L ? __expf(x - nm) : 0.f;
                sP[sr][sg + 8 * k2] = p;
                lsum += p;
            }
            lsum += __shfl_xor_sync(0xffffffffu, lsum, 4);
            lsum += __shfl_xor_sync(0xffffffffu, lsum, 2);
            lsum += __shfl_xor_sync(0xffffffffu, lsum, 1);
            if (sg == 0) {
                float corr = __expf(mold - nm);
                s_l[sr] = s_l[sr] * corr + lsum;
                s_m[sr] = nm;
                s_c[sr] = corr;
            }
        }
        __syncthreads();

        // ============== GEMM2: O[32][512] += P[32][256] * V[256][512] ======
        {
            // rescale running O
#pragma unroll
            for (int i = 0; i < 8; i++) {
                float cc = s_c[8 * rg + i];
                ull c2 = pack2(cc, cc);
                o2[i][0][0] = mul2_(o2[i][0][0], c2);
                o2[i][0][1] = mul2_(o2[i][0][1], c2);
                o2[i][1][0] = mul2_(o2[i][1][0], c2);
                o2[i][1][1] = mul2_(o2[i][1][1], c2);
            }

            const float* gV = Vp + ((size_t)(b * KK + kt * NT)) * DD;
            float4 pv0 = *(const float4*)(gV + (size_t)vr0 * DD + 4 * vu);
            float4 pv1 = *(const float4*)(gV + (size_t)(vr0 + 2) * DD + 4 * vu);
            *(float4*)&sV[0][vr0][4 * vu]     = pv0;
            *(float4*)&sV[0][vr0 + 2][4 * vu] = pv1;
            __syncthreads();
#pragma unroll 1
            for (int vc = 0; vc < 64; vc++) {
                if (vc < 63) {
                    const float* gVn = gV + (size_t)((vc + 1) * 4) * DD;
                    pv0 = *(const float4*)(gVn + (size_t)vr0 * DD + 4 * vu);
                    pv1 = *(const float4*)(gVn + (size_t)(vr0 + 2) * DD + 4 * vu);
                }
                const int vb = vc & 1;
#pragma unroll
                for (int jj = 0; jj < 2; jj++) {
                    float2 pp[8];
#pragma unroll
                    for (int i = 0; i < 8; i++)
                        pp[i] = *(const float2*)&sP[8 * rg + i][4 * vc + 2 * jj];
#pragma unroll
                    for (int jn = 0; jn < 2; jn++) {
                        const float* vrow = &sV[vb][2 * jj + jn][0];
                        ulonglong2 vv0 = *(const ulonglong2*)(vrow + 4 * cg);
                        ulonglong2 vv1 = *(const ulonglong2*)(vrow + 4 * cg + 256);
#pragma unroll
                        for (int i = 0; i < 8; i++) {
                            float pv = jn ? pp[i].y : pp[i].x;
                            ull pd = pack2(pv, pv);
                            o2[i][0][0] = fma2(pd, vv0.x, o2[i][0][0]);
                            o2[i][0][1] = fma2(pd, vv0.y, o2[i][0][1]);
                            o2[i][1][0] = fma2(pd, vv1.x, o2[i][1][0]);
                            o2[i][1][1] = fma2(pd, vv1.y, o2[i][1][1]);
                        }
                    }
                }
                if (vc < 63) {
                    const int nb = (vc + 1) & 1;
                    *(float4*)&sV[nb][vr0][4 * vu]     = pv0;
                    *(float4*)&sV[nb][vr0 + 2][4 * vu] = pv1;
                }
                __syncthreads();
            }
        }
    }  // tile loop

    // ============== finalize with analytic masked-tail ======================
#pragma unroll
    for (int i = 0; i < 8; i++) {
        const int r = 8 * rg + i;
        float mr = s_m[r];
        float lr_ = s_l[r];
        float M  = fmaxf(mr, 0.f);
        float c  = __expf(mr - M);
        float w0 = __expf(-M);
        float inv = 1.f / (lr_ * c + (float)(KK - L) * w0);
        float* orow = out + ((size_t)(b * QQ + qbase + r)) * DD;
#pragma unroll
        for (int s = 0; s < 2; s++) {
            const int cb2 = 4 * cg + 256 * s;
            float4 tv = *(const float4*)&s_vt[cb2];
            float x0, x1, x2, x3;
            unpack2(o2[i][s][0], x0, x1);
            unpack2(o2[i][s][1], x2, x3);
            float4 r4;
            r4.x = (x0 * c + w0 * tv.x) * inv;
            r4.y = (x1 * c + w0 * tv.y) * inv;
            r4.z = (x2 * c + w0 * tv.z) * inv;
            r4.w = (x3 * c + w0 * tv.w) * inv;
            *(float4*)(orow + cb2) = r4;
        }
    }
}

// ---------------------------------------------------------------------------
extern "C" void kernel_launch(void* const* d_in, const int* in_sizes, int n_in,
                              void* d_out, int out_size) {
    const float* Q    = (const float*)d_in[0];
    const float* K    = (const float*)d_in[1];
    const float* V    = (const float*)d_in[2];
    const int*   lens = (const int*)d_in[3];
    float* out = (float*)d_out;

    cudaFuncSetAttribute(attn_kernel,
                         cudaFuncAttributeMaxDynamicSharedMemorySize,
                         SMEM_BYTES);

    vtail_partial_kernel<<<dim3(16, BB), 512>>>(V, lens);
    attn_kernel<<<512, 256, SMEM_BYTES>>>(Q, K, V, lens, out);
}